// round 1
// baseline (speedup 1.0000x reference)
#include <cuda_runtime.h>
#include <cuda_bf16.h>
#include <mma.h>

using namespace nvcuda;

#define BATCH 1024
#define NG    978
#define NGP   992          // NG padded to multiple of 16 for wmma K
#define NNODE (BATCH*NG)   // 1001472
#define NEDGE 20480000
#define H1    2048
#define H2    100
#define H2P   128          // fc2 N padded
#define MROWS 2048         // both encoders stacked: 2*BATCH

// -------- device scratch (BSS => zero-initialized; pad regions never written) --------
__device__ float2        g_xin[NNODE];          // interleaved {x1, x2}
__device__ float2        g_agg[NNODE];          // interleaved {agg1, agg2}
__device__ __nv_bfloat16 g_H [MROWS*NGP];       // relu(gcn) both encoders, K-padded
__device__ __nv_bfloat16 g_W1[NGP*H1];          // fc1 weight bf16, K-padded rows stay 0
__device__ float         g_C1[MROWS*H1];        // fc1 fp32 accum
__device__ __nv_bfloat16 g_A2[MROWS*H1];        // relu(fc1) bf16
__device__ __nv_bfloat16 g_W2[H1*H2P];          // fc2 weight bf16, cols 100..127 stay 0
__device__ float         g_O [MROWS*H2P];       // fc2 output (split-K atomic target)

// -------- K0: pack inputs as float2, zero accumulators --------
__global__ void __launch_bounds__(256) k_pack(const float* __restrict__ x1,
                                              const float* __restrict__ x2) {
    int i = blockIdx.x * 256 + threadIdx.x;          // grid sized exactly
    g_xin[i] = make_float2(x1[i], x2[i]);
    g_agg[i] = make_float2(0.f, 0.f);
}

// -------- K1: convert weights to bf16, zero split-K output --------
__global__ void __launch_bounds__(256) k_prep(const float* __restrict__ w1,
                                              const float* __restrict__ w2) {
    int i = blockIdx.x * 256 + threadIdx.x;
    if (i < NG * H1) { g_W1[i] = __float2bfloat16(w1[i]); return; }
    i -= NG * H1;
    if (i < H1 * H2) {
        int k = i / H2, c = i - k * H2;
        g_W2[k * H2P + c] = __float2bfloat16(w2[i]);
        return;
    }
    i -= H1 * H2;
    if (i < MROWS * H2P) g_O[i] = 0.f;
}

// -------- K2: fused edge gather + vector scatter-add (both encoders at once) --------
__device__ __forceinline__ void edge1(int s, int d) {
    float2 v = __ldcg(&g_xin[s]);
    asm volatile("red.global.add.v2.f32 [%0], {%1,%2};"
                 :: "l"(g_agg + d), "f"(v.x), "f"(v.y) : "memory");
}

__global__ void __launch_bounds__(256) k_edges(const int* __restrict__ edges) {
    int t = blockIdx.x * 256 + threadIdx.x;          // < NEDGE/4 exactly
    int4 s = reinterpret_cast<const int4*>(edges)[t];
    int4 d = reinterpret_cast<const int4*>(edges + NEDGE)[t];
    edge1(s.x, d.x);
    edge1(s.y, d.y);
    edge1(s.z, d.z);
    edge1(s.w, d.w);
}

// -------- K3: h = relu(w*agg + b), write bf16 into padded stacked matrix --------
__global__ void __launch_bounds__(256) k_h(const float* __restrict__ gw,
                                           const float* __restrict__ gb) {
    int i = blockIdx.x * 256 + threadIdx.x;          // < NNODE exactly
    float w = *gw, b = *gb;
    float2 a = g_agg[i];
    int bi = i / NG;
    int g  = i - bi * NG;
    g_H[bi * NGP + g]           = __float2bfloat16(fmaxf(w * a.x + b, 0.f));
    g_H[(BATCH + bi) * NGP + g] = __float2bfloat16(fmaxf(w * a.y + b, 0.f));
}

// -------- K4/K6: wmma bf16 GEMM, MODE 0 = fc1 (direct), MODE 1 = fc2 (split-K atomic) --------
template <int MODE>
__global__ void __launch_bounds__(256) k_gemm() {
    constexpr int BM = 128, BN = 128, BK = 32;
    constexpr int Kdim   = (MODE == 0) ? NGP : H1;
    constexpr int lda    = (MODE == 0) ? NGP : H1;
    constexpr int ldb    = (MODE == 0) ? H1  : H2P;
    constexpr int ldc    = (MODE == 0) ? H1  : H2P;
    constexpr int SPLITK = (MODE == 0) ? 1   : 4;
    const __nv_bfloat16* __restrict__ A = (MODE == 0) ? g_H  : g_A2;
    const __nv_bfloat16* __restrict__ B = (MODE == 0) ? g_W1 : g_W2;
    float* C = (MODE == 0) ? g_C1 : g_O;

    __shared__ __nv_bfloat16 As[BM][BK + 16];
    __shared__ __nv_bfloat16 Bs[BK][BN + 16];
    __shared__ float stage[8][256];

    const int tid    = threadIdx.x;
    const int warpId = tid >> 5;
    const int lane   = tid & 31;
    const int m0 = blockIdx.x * BM;
    const int n0 = blockIdx.y * BN;
    constexpr int KCH = Kdim / SPLITK;
    const int kbeg = blockIdx.z * KCH;
    const int wr = warpId & 1;   // 2 row groups of 64
    const int wc = warpId >> 1;  // 4 col groups of 32

    wmma::fragment<wmma::accumulator, 16, 16, 16, float> acc[4][2];
#pragma unroll
    for (int i = 0; i < 4; i++)
#pragma unroll
        for (int j = 0; j < 2; j++) wmma::fill_fragment(acc[i][j], 0.0f);

    for (int k0 = kbeg; k0 < kbeg + KCH; k0 += BK) {
#pragma unroll
        for (int l = 0; l < 2; l++) {
            int idx = tid + l * 256;
            int row = idx >> 2, seg = idx & 3;
            *reinterpret_cast<int4*>(&As[row][seg * 8]) =
                *reinterpret_cast<const int4*>(A + (size_t)(m0 + row) * lda + (k0 + seg * 8));
        }
#pragma unroll
        for (int l = 0; l < 2; l++) {
            int idx = tid + l * 256;
            int row = idx >> 4, seg = idx & 15;
            *reinterpret_cast<int4*>(&Bs[row][seg * 8]) =
                *reinterpret_cast<const int4*>(B + (size_t)(k0 + row) * ldb + (n0 + seg * 8));
        }
        __syncthreads();
#pragma unroll
        for (int kk = 0; kk < BK; kk += 16) {
            wmma::fragment<wmma::matrix_a, 16, 16, 16, __nv_bfloat16, wmma::row_major> af[4];
            wmma::fragment<wmma::matrix_b, 16, 16, 16, __nv_bfloat16, wmma::row_major> bf_[2];
#pragma unroll
            for (int i = 0; i < 4; i++)
                wmma::load_matrix_sync(af[i], &As[wr * 64 + i * 16][kk], BK + 16);
#pragma unroll
            for (int j = 0; j < 2; j++)
                wmma::load_matrix_sync(bf_[j], &Bs[kk][wc * 32 + j * 16], BN + 16);
#pragma unroll
            for (int i = 0; i < 4; i++)
#pragma unroll
                for (int j = 0; j < 2; j++)
                    wmma::mma_sync(acc[i][j], af[i], bf_[j], acc[i][j]);
        }
        __syncthreads();
    }

    if (MODE == 0) {
#pragma unroll
        for (int i = 0; i < 4; i++)
#pragma unroll
            for (int j = 0; j < 2; j++)
                wmma::store_matrix_sync(
                    C + (size_t)(m0 + wr * 64 + i * 16) * ldc + (n0 + wc * 32 + j * 16),
                    acc[i][j], ldc, wmma::mem_row_major);
    } else {
#pragma unroll
        for (int i = 0; i < 4; i++)
#pragma unroll
            for (int j = 0; j < 2; j++) {
                wmma::store_matrix_sync(&stage[warpId][0], acc[i][j], 16, wmma::mem_row_major);
                __syncwarp();
                float* cp = C + (size_t)(m0 + wr * 64 + i * 16) * ldc + (n0 + wc * 32 + j * 16);
#pragma unroll
                for (int e = 0; e < 8; e++) {
                    int idx = lane + e * 32;
                    atomicAdd(&cp[(idx >> 4) * ldc + (idx & 15)], stage[warpId][idx]);
                }
                __syncwarp();
            }
    }
}

// -------- K5: fc1 epilogue: bias + relu + bf16 --------
__global__ void __launch_bounds__(256) k_ep1(const float* __restrict__ b1) {
    int i = blockIdx.x * 256 + threadIdx.x;          // < MROWS*H1 exactly
    float v = g_C1[i] + b1[i & (H1 - 1)];
    g_A2[i] = __float2bfloat16(fmaxf(v, 0.f));
}

// -------- K7: r^2 + predictor MLP, one warp per batch row --------
__global__ void __launch_bounds__(256) k_final(const float* __restrict__ others,
                                               const float* __restrict__ fc2b,
                                               const float* __restrict__ m1w,
                                               const float* __restrict__ m1b,
                                               const float* __restrict__ m2w,
                                               const float* __restrict__ m2b,
                                               float* __restrict__ out) {
    int row  = (blockIdx.x * blockDim.x + threadIdx.x) >> 5;  // 0..1023
    int lane = threadIdx.x & 31;
    float a[4], b[4];
    float sa = 0.f, sb = 0.f;
#pragma unroll
    for (int i = 0; i < 4; i++) {
        int c = lane + i * 32;
        float av = 0.f, bv = 0.f;
        if (c < H2) {
            float bias = fc2b[c];
            av = g_O[row * H2P + c] + bias;
            bv = g_O[(BATCH + row) * H2P + c] + bias;
        }
        a[i] = av; b[i] = bv; sa += av; sb += bv;
    }
#pragma unroll
    for (int o = 16; o > 0; o >>= 1) {
        sa += __shfl_xor_sync(~0u, sa, o);
        sb += __shfl_xor_sync(~0u, sb, o);
    }
    float ma = sa * (1.f / H2), mb = sb * (1.f / H2);
    float sab = 0.f, saa = 0.f, sbb = 0.f;
#pragma unroll
    for (int i = 0; i < 4; i++) {
        int c = lane + i * 32;
        if (c < H2) {
            float da = a[i] - ma, db = b[i] - mb;
            sab += da * db; saa += da * da; sbb += db * db;
        }
    }
#pragma unroll
    for (int o = 16; o > 0; o >>= 1) {
        sab += __shfl_xor_sync(~0u, sab, o);
        saa += __shfl_xor_sync(~0u, saa, o);
        sbb += __shfl_xor_sync(~0u, sbb, o);
    }
    if (lane == 0) {
        float corr = sab / (sqrtf(saa) * sqrtf(sbb));
        float z[5];
        z[0] = corr * corr;
#pragma unroll
        for (int i = 0; i < 4; i++) z[i + 1] = others[row * 4 + i];
        float h[4];
#pragma unroll
        for (int j = 0; j < 4; j++) {
            float s = m1b[j];
#pragma unroll
            for (int i = 0; i < 5; i++) s += z[i] * m1w[i * 4 + j];
            h[j] = fmaxf(s, 0.f);
        }
#pragma unroll
        for (int k = 0; k < 2; k++) {
            float s = m2b[k];
#pragma unroll
            for (int j = 0; j < 4; j++) s += h[j] * m2w[j * 2 + k];
            out[row * 2 + k] = s;
        }
    }
}

extern "C" void kernel_launch(void* const* d_in, const int* in_sizes, int n_in,
                              void* d_out, int out_size) {
    const float* in1    = (const float*)d_in[0];
    const float* in2    = (const float*)d_in[1];
    const int*   edges  = (const int*)d_in[2];
    const float* others = (const float*)d_in[3];
    const float* gw     = (const float*)d_in[4];
    const float* gb     = (const float*)d_in[5];
    const float* w1     = (const float*)d_in[6];
    const float* b1     = (const float*)d_in[7];
    const float* w2     = (const float*)d_in[8];
    const float* b2     = (const float*)d_in[9];
    const float* m1w    = (const float*)d_in[10];
    const float* m1b    = (const float*)d_in[11];
    const float* m2w    = (const float*)d_in[12];
    const float* m2b    = (const float*)d_in[13];
    float* out = (float*)d_out;

    k_pack <<<NNODE / 256, 256>>>(in1, in2);                 // 3912 blocks
    k_prep <<<9648, 256>>>(w1, w2);                          // W bf16 + zero g_O
    k_edges<<<NEDGE / 4 / 256, 256>>>(edges);                // 20000 blocks
    k_h    <<<NNODE / 256, 256>>>(gw, gb);
    k_gemm<0><<<dim3(16, 16, 1), 256>>>();                   // fc1: 2048x2048x992
    k_ep1  <<<MROWS * H1 / 256, 256>>>(b1);
    k_gemm<1><<<dim3(16, 1, 4), 256>>>();                    // fc2: 2048x128x2048 split-K
    k_final<<<128, 256>>>(others, b2, m1w, m1b, m2w, m2b, out);
}

// round 2
// speedup vs baseline: 1.1323x; 1.1323x over previous
#include <cuda_runtime.h>
#include <cuda_bf16.h>
#include <mma.h>

using namespace nvcuda;

#define BATCH 1024
#define NG    978
#define NGP   992          // NG padded to multiple of 32 for GEMM K
#define NNODE (BATCH*NG)   // 1001472
#define NEDGE 20480000
#define H1    2048
#define H2    100
#define H2P   128          // fc2 N padded
#define MROWS 2048         // both encoders stacked: 2*BATCH
#define SPLITK2 8

// -------- device scratch (BSS => zero-initialized; pad regions never written) --------
__device__ float2        g_xin[NNODE];            // interleaved {x1, x2}
__device__ float2        g_agg[NNODE];            // interleaved {agg1, agg2}
__device__ __nv_bfloat16 g_H [MROWS*NGP];         // relu(gcn) both encoders, K-padded
__device__ __nv_bfloat16 g_W1[NGP*H1];            // fc1 weight bf16, K-pad rows stay 0
__device__ __nv_bfloat16 g_A2[MROWS*H1];          // relu(fc1 + b1) bf16
__device__ __nv_bfloat16 g_W2[H1*H2P];            // fc2 weight bf16, cols 100..127 stay 0
__device__ float         g_Op[SPLITK2][MROWS*H2P];// fc2 split-K partials

// -------- cp.async helpers --------
__device__ __forceinline__ void cp16(void* smem_dst, const void* gmem_src) {
    unsigned saddr = (unsigned)__cvta_generic_to_shared(smem_dst);
    asm volatile("cp.async.cg.shared.global [%0], [%1], 16;" :: "r"(saddr), "l"(gmem_src));
}
#define CP_COMMIT()  asm volatile("cp.async.commit_group;")
#define CP_WAIT(N)   asm volatile("cp.async.wait_group %0;" :: "n"(N))

// -------- K0: pack inputs as float2, zero accumulators --------
__global__ void __launch_bounds__(256) k_pack(const float* __restrict__ x1,
                                              const float* __restrict__ x2) {
    int i = blockIdx.x * 256 + threadIdx.x;          // grid sized exactly
    g_xin[i] = make_float2(x1[i], x2[i]);
    g_agg[i] = make_float2(0.f, 0.f);
}

// -------- K1: convert weights to bf16 --------
__global__ void __launch_bounds__(256) k_prep(const float* __restrict__ w1,
                                              const float* __restrict__ w2) {
    int i = blockIdx.x * 256 + threadIdx.x;
    if (i < NG * H1) { g_W1[i] = __float2bfloat16(w1[i]); return; }
    i -= NG * H1;
    if (i < H1 * H2) {
        int k = i / H2, c = i - k * H2;
        g_W2[k * H2P + c] = __float2bfloat16(w2[i]);
    }
}

// -------- K2: fused edge gather + vector scatter-add, 8 edges/thread --------
__device__ __forceinline__ void redv2(int d, float2 v) {
    asm volatile("red.global.add.v2.f32 [%0], {%1,%2};"
                 :: "l"(g_agg + d), "f"(v.x), "f"(v.y) : "memory");
}

__global__ void __launch_bounds__(256) k_edges(const int* __restrict__ edges) {
    long t = blockIdx.x * 256 + threadIdx.x;         // < NEDGE/8 exactly
    const int4* sp = reinterpret_cast<const int4*>(edges);
    const int4* dp = reinterpret_cast<const int4*>(edges + NEDGE);
    int4 s0 = sp[2 * t], s1 = sp[2 * t + 1];
    int4 d0 = dp[2 * t], d1 = dp[2 * t + 1];
    // batch all gathers first (max MLP), then fire the reductions
    float2 v0 = __ldcg(&g_xin[s0.x]);
    float2 v1 = __ldcg(&g_xin[s0.y]);
    float2 v2 = __ldcg(&g_xin[s0.z]);
    float2 v3 = __ldcg(&g_xin[s0.w]);
    float2 v4 = __ldcg(&g_xin[s1.x]);
    float2 v5 = __ldcg(&g_xin[s1.y]);
    float2 v6 = __ldcg(&g_xin[s1.z]);
    float2 v7 = __ldcg(&g_xin[s1.w]);
    redv2(d0.x, v0); redv2(d0.y, v1); redv2(d0.z, v2); redv2(d0.w, v3);
    redv2(d1.x, v4); redv2(d1.y, v5); redv2(d1.z, v6); redv2(d1.w, v7);
}

// -------- K3: h = relu(w*agg + b), write bf16 into padded stacked matrix --------
__global__ void __launch_bounds__(256) k_h(const float* __restrict__ gw,
                                           const float* __restrict__ gb) {
    int i = blockIdx.x * 256 + threadIdx.x;          // < NNODE exactly
    float w = *gw, b = *gb;
    float2 a = g_agg[i];
    int bi = i / NG;
    int g  = i - bi * NG;
    g_H[bi * NGP + g]           = __float2bfloat16(fmaxf(w * a.x + b, 0.f));
    g_H[(BATCH + bi) * NGP + g] = __float2bfloat16(fmaxf(w * a.y + b, 0.f));
}

// -------- K4/K5: double-buffered cp.async wmma GEMM --------
// MODE 0: fc1  A=g_H(2048x992) B=g_W1(992x2048)  -> fused bias+relu -> g_A2 (bf16)
// MODE 1: fc2  A=g_A2(2048x2048) B=g_W2(2048x128) -> split-K partials g_Op[z] (f32)
template <int MODE>
__global__ void __launch_bounds__(256) k_gemm(const float* __restrict__ bias) {
    constexpr int BM = 128, BN = 128, BK = 32;
    constexpr int Kdim = (MODE == 0) ? NGP : H1;
    constexpr int lda  = (MODE == 0) ? NGP : H1;
    constexpr int ldb  = (MODE == 0) ? H1  : H2P;
    constexpr int SPLITK = (MODE == 0) ? 1 : SPLITK2;
    constexpr int KCH  = Kdim / SPLITK;
    constexpr int NITER = KCH / BK;
    constexpr int AP = BK + 8, BP = BN + 8;

    const __nv_bfloat16* __restrict__ A = (MODE == 0) ? g_H  : g_A2;
    const __nv_bfloat16* __restrict__ B = (MODE == 0) ? g_W1 : g_W2;

    __shared__ __nv_bfloat16 As[2][BM][AP];
    __shared__ __nv_bfloat16 Bs[2][BK][BP];
    __shared__ float stage[8][256];

    const int tid    = threadIdx.x;
    const int warpId = tid >> 5;
    const int lane   = tid & 31;
    const int m0 = blockIdx.x * BM;
    const int n0 = blockIdx.y * BN;
    const int kbeg = blockIdx.z * KCH;
    const int wr = warpId & 1;   // 2 row groups of 64
    const int wc = warpId >> 1;  // 4 col groups of 32

    // per-thread cp.async coordinates (2 chunks of 16B for each of A,B per stage)
    const int ar0 = (tid)       >> 2, ac0 = ((tid)       & 3) * 8;
    const int ar1 = (tid + 256) >> 2, ac1 = ((tid + 256) & 3) * 8;
    const int br0 = (tid)       >> 4, bc0 = ((tid)       & 15) * 8;
    const int br1 = (tid + 256) >> 4, bc1 = ((tid + 256) & 15) * 8;

    auto fill = [&](int st, int k0) {
        cp16(&As[st][ar0][ac0], A + (size_t)(m0 + ar0) * lda + (k0 + ac0));
        cp16(&As[st][ar1][ac1], A + (size_t)(m0 + ar1) * lda + (k0 + ac1));
        cp16(&Bs[st][br0][bc0], B + (size_t)(k0 + br0) * ldb + (n0 + bc0));
        cp16(&Bs[st][br1][bc1], B + (size_t)(k0 + br1) * ldb + (n0 + bc1));
    };

    wmma::fragment<wmma::accumulator, 16, 16, 16, float> acc[4][2];
#pragma unroll
    for (int i = 0; i < 4; i++)
#pragma unroll
        for (int j = 0; j < 2; j++) wmma::fill_fragment(acc[i][j], 0.0f);

    fill(0, kbeg);
    CP_COMMIT();

    for (int it = 0; it < NITER; it++) {
        int cur = it & 1;
        if (it + 1 < NITER) { fill(cur ^ 1, kbeg + (it + 1) * BK); CP_COMMIT(); }
        if (it + 1 < NITER) { CP_WAIT(1); } else { CP_WAIT(0); }
        __syncthreads();
#pragma unroll
        for (int kk = 0; kk < BK; kk += 16) {
            wmma::fragment<wmma::matrix_a, 16, 16, 16, __nv_bfloat16, wmma::row_major> af[4];
            wmma::fragment<wmma::matrix_b, 16, 16, 16, __nv_bfloat16, wmma::row_major> bf_[2];
#pragma unroll
            for (int i = 0; i < 4; i++)
                wmma::load_matrix_sync(af[i], &As[cur][wr * 64 + i * 16][kk], AP);
#pragma unroll
            for (int j = 0; j < 2; j++)
                wmma::load_matrix_sync(bf_[j], &Bs[cur][kk][wc * 32 + j * 16], BP);
#pragma unroll
            for (int i = 0; i < 4; i++)
#pragma unroll
                for (int j = 0; j < 2; j++)
                    wmma::mma_sync(acc[i][j], af[i], bf_[j], acc[i][j]);
        }
        __syncthreads();
    }

    if (MODE == 1) {
        float* C = g_Op[blockIdx.z];
#pragma unroll
        for (int i = 0; i < 4; i++)
#pragma unroll
            for (int j = 0; j < 2; j++)
                wmma::store_matrix_sync(
                    C + (size_t)(m0 + wr * 64 + i * 16) * H2P + (n0 + wc * 32 + j * 16),
                    acc[i][j], H2P, wmma::mem_row_major);
    } else {
        // fused epilogue: bias + relu + bf16 -> g_A2
#pragma unroll
        for (int i = 0; i < 4; i++)
#pragma unroll
            for (int j = 0; j < 2; j++) {
                wmma::store_matrix_sync(&stage[warpId][0], acc[i][j], 16, wmma::mem_row_major);
                __syncwarp();
                int row = m0 + wr * 64 + i * 16 + (lane >> 1);
                int col = n0 + wc * 32 + j * 16 + (lane & 1) * 8;
                const float* s = &stage[warpId][(lane >> 1) * 16 + (lane & 1) * 8];
                __nv_bfloat16 v[8];
#pragma unroll
                for (int e = 0; e < 8; e++)
                    v[e] = __float2bfloat16(fmaxf(s[e] + bias[col + e], 0.f));
                *reinterpret_cast<int4*>(&g_A2[(size_t)row * H1 + col]) =
                    *reinterpret_cast<int4*>(v);
                __syncwarp();
            }
    }
}

// -------- K6: r^2 + predictor MLP, one warp per batch row --------
__global__ void __launch_bounds__(256) k_final(const float* __restrict__ others,
                                               const float* __restrict__ fc2b,
                                               const float* __restrict__ m1w,
                                               const float* __restrict__ m1b,
                                               const float* __restrict__ m2w,
                                               const float* __restrict__ m2b,
                                               float* __restrict__ out) {
    int row  = (blockIdx.x * blockDim.x + threadIdx.x) >> 5;  // 0..1023
    int lane = threadIdx.x & 31;
    float a[4], b[4];
    float sa = 0.f, sb = 0.f;
#pragma unroll
    for (int i = 0; i < 4; i++) {
        int c = lane + i * 32;
        float av = 0.f, bv = 0.f;
        if (c < H2) {
            float bias = fc2b[c];
#pragma unroll
            for (int z = 0; z < SPLITK2; z++) {
                av += g_Op[z][row * H2P + c];
                bv += g_Op[z][(BATCH + row) * H2P + c];
            }
            av += bias; bv += bias;
        }
        a[i] = av; b[i] = bv; sa += av; sb += bv;
    }
#pragma unroll
    for (int o = 16; o > 0; o >>= 1) {
        sa += __shfl_xor_sync(~0u, sa, o);
        sb += __shfl_xor_sync(~0u, sb, o);
    }
    float ma = sa * (1.f / H2), mb = sb * (1.f / H2);
    float sab = 0.f, saa = 0.f, sbb = 0.f;
#pragma unroll
    for (int i = 0; i < 4; i++) {
        int c = lane + i * 32;
        if (c < H2) {
            float da = a[i] - ma, db = b[i] - mb;
            sab += da * db; saa += da * da; sbb += db * db;
        }
    }
#pragma unroll
    for (int o = 16; o > 0; o >>= 1) {
        sab += __shfl_xor_sync(~0u, sab, o);
        saa += __shfl_xor_sync(~0u, saa, o);
        sbb += __shfl_xor_sync(~0u, sbb, o);
    }
    if (lane == 0) {
        float corr = sab / (sqrtf(saa) * sqrtf(sbb));
        float z[5];
        z[0] = corr * corr;
#pragma unroll
        for (int i = 0; i < 4; i++) z[i + 1] = others[row * 4 + i];
        float h[4];
#pragma unroll
        for (int j = 0; j < 4; j++) {
            float s = m1b[j];
#pragma unroll
            for (int i = 0; i < 5; i++) s += z[i] * m1w[i * 4 + j];
            h[j] = fmaxf(s, 0.f);
        }
#pragma unroll
        for (int k = 0; k < 2; k++) {
            float s = m2b[k];
#pragma unroll
            for (int j = 0; j < 4; j++) s += h[j] * m2w[j * 2 + k];
            out[row * 2 + k] = s;
        }
    }
}

extern "C" void kernel_launch(void* const* d_in, const int* in_sizes, int n_in,
                              void* d_out, int out_size) {
    const float* in1    = (const float*)d_in[0];
    const float* in2    = (const float*)d_in[1];
    const int*   edges  = (const int*)d_in[2];
    const float* others = (const float*)d_in[3];
    const float* gw     = (const float*)d_in[4];
    const float* gb     = (const float*)d_in[5];
    const float* w1     = (const float*)d_in[6];
    const float* b1     = (const float*)d_in[7];
    const float* w2     = (const float*)d_in[8];
    const float* b2     = (const float*)d_in[9];
    const float* m1w    = (const float*)d_in[10];
    const float* m1b    = (const float*)d_in[11];
    const float* m2w    = (const float*)d_in[12];
    const float* m2b    = (const float*)d_in[13];
    float* out = (float*)d_out;

    k_pack <<<NNODE / 256, 256>>>(in1, in2);                 // 3912 blocks
    k_prep <<<(NG * H1 + H1 * H2 + 255) / 256, 256>>>(w1, w2);
    k_edges<<<NEDGE / 8 / 256, 256>>>(edges);                // 10000 blocks
    k_h    <<<NNODE / 256, 256>>>(gw, gb);
    k_gemm<0><<<dim3(16, 16, 1), 256>>>(b1);                 // fc1 + fused bias/relu
    k_gemm<1><<<dim3(16, 1, SPLITK2), 256>>>(nullptr);       // fc2 split-K partials
    k_final<<<128, 256>>>(others, b2, m1w, m1b, m2w, m2b, out);
}

// round 4
// speedup vs baseline: 1.1870x; 1.0483x over previous
#include <cuda_runtime.h>
#include <cuda_bf16.h>
#include <mma.h>

using namespace nvcuda;

#define BATCH 1024
#define NG    978
#define NGP   992          // NG padded to multiple of 32 for GEMM K
#define NNODE (BATCH*NG)   // 1001472
#define NEDGE 20480000
#define H1    2048
#define H2    100
#define H2P   128          // fc2 N padded
#define MROWS 2048         // both encoders stacked: 2*BATCH
#define SPLITK2 8

// -------- device scratch (BSS => zero-initialized; pad regions never written) --------
__device__ float2        g_xin[NNODE];            // interleaved {x1, x2}
__device__ float2        g_agg[NNODE];            // interleaved {agg1, agg2}
__device__ __nv_bfloat16 g_H [MROWS*NGP];         // relu(gcn) both encoders, K-padded
__device__ __nv_bfloat16 g_W1[NGP*H1];            // fc1 weight bf16, K-pad rows stay 0
__device__ __nv_bfloat16 g_A2[MROWS*H1];          // relu(fc1 + b1) bf16
__device__ __nv_bfloat16 g_W2[H1*H2P];            // fc2 weight bf16, cols 100..127 stay 0
__device__ float         g_Op[SPLITK2][MROWS*H2P];// fc2 split-K partials

// -------- cp.async helpers --------
__device__ __forceinline__ void cp16(void* smem_dst, const void* gmem_src) {
    unsigned saddr = (unsigned)__cvta_generic_to_shared(smem_dst);
    asm volatile("cp.async.cg.shared.global [%0], [%1], 16;" :: "r"(saddr), "l"(gmem_src));
}
#define CP_COMMIT()  asm volatile("cp.async.commit_group;")
#define CP_WAIT(N)   asm volatile("cp.async.wait_group %0;" :: "n"(N))

// -------- K0: pack inputs as float2 pairs, zero accumulators --------
__global__ void __launch_bounds__(256) k_pack(const float* __restrict__ x1,
                                              const float* __restrict__ x2) {
    int i = blockIdx.x * 256 + threadIdx.x;           // < NNODE/2 exactly
    float2 a = reinterpret_cast<const float2*>(x1)[i];
    float2 b = reinterpret_cast<const float2*>(x2)[i];
    reinterpret_cast<float4*>(g_xin)[i] = make_float4(a.x, b.x, a.y, b.y);
    reinterpret_cast<float4*>(g_agg)[i] = make_float4(0.f, 0.f, 0.f, 0.f);
}

// -------- K1: convert weights to bf16 --------
__global__ void __launch_bounds__(256) k_prep(const float* __restrict__ w1,
                                              const float* __restrict__ w2) {
    int i = blockIdx.x * 256 + threadIdx.x;
    if (i < NG * H1) { g_W1[i] = __float2bfloat16(w1[i]); return; }
    i -= NG * H1;
    if (i < H1 * H2) {
        int k = i / H2, c = i - k * H2;
        g_W2[k * H2P + c] = __float2bfloat16(w2[i]);
    }
}

// -------- K2: fused edge gather + vector scatter-add, 8 edges/thread --------
// Edge-index stream is read once: use .cs (evict-first) so it doesn't evict
// the L2-resident g_xin/g_agg working set that the random gathers/reds hit.
__device__ __forceinline__ void redv2(int d, float2 v) {
    asm volatile("red.global.add.v2.f32 [%0], {%1,%2};"
                 :: "l"(g_agg + d), "f"(v.x), "f"(v.y) : "memory");
}

__global__ void __launch_bounds__(256) k_edges(const int* __restrict__ edges) {
    long t = blockIdx.x * 256 + threadIdx.x;          // < NEDGE/8 exactly
    const int4* sp = reinterpret_cast<const int4*>(edges);
    const int4* dp = reinterpret_cast<const int4*>(edges + NEDGE);
    int4 s0 = __ldcs(sp + 2 * t), s1 = __ldcs(sp + 2 * t + 1);
    int4 d0 = __ldcs(dp + 2 * t), d1 = __ldcs(dp + 2 * t + 1);
    // batch all gathers first (max MLP), then fire the reductions
    float2 v0 = __ldcg(&g_xin[s0.x]);
    float2 v1 = __ldcg(&g_xin[s0.y]);
    float2 v2 = __ldcg(&g_xin[s0.z]);
    float2 v3 = __ldcg(&g_xin[s0.w]);
    float2 v4 = __ldcg(&g_xin[s1.x]);
    float2 v5 = __ldcg(&g_xin[s1.y]);
    float2 v6 = __ldcg(&g_xin[s1.z]);
    float2 v7 = __ldcg(&g_xin[s1.w]);
    redv2(d0.x, v0); redv2(d0.y, v1); redv2(d0.z, v2); redv2(d0.w, v3);
    redv2(d1.x, v4); redv2(d1.y, v5); redv2(d1.z, v6); redv2(d1.w, v7);
}

// -------- K3: h = relu(w*agg + b), bf16, 2 nodes/thread --------
__global__ void __launch_bounds__(256) k_h(const float* __restrict__ gw,
                                           const float* __restrict__ gb) {
    int i = blockIdx.x * 256 + threadIdx.x;           // < NNODE/2 exactly
    float w = *gw, b = *gb;
    float4 v = reinterpret_cast<const float4*>(g_agg)[i];
    int n0 = 2 * i;
    int bi = n0 / NG;
    int g  = n0 - bi * NG;                            // always even
    __nv_bfloat162 e1 = __floats2bfloat162_rn(fmaxf(w * v.x + b, 0.f), fmaxf(w * v.z + b, 0.f));
    __nv_bfloat162 e2 = __floats2bfloat162_rn(fmaxf(w * v.y + b, 0.f), fmaxf(w * v.w + b, 0.f));
    *reinterpret_cast<__nv_bfloat162*>(&g_H[(size_t)bi * NGP + g]) = e1;
    *reinterpret_cast<__nv_bfloat162*>(&g_H[(size_t)(BATCH + bi) * NGP + g]) = e2;
}

// -------- K4/K5: double-buffered cp.async wmma GEMM, 64x64 warp tiles --------
// 128 threads = 4 warps in 2x2 grid, each warp 64x64 (4x4 frags of 16x16).
// MODE 0: fc1  A=g_H(2048x992)  B=g_W1(992x2048)  -> fused bias+relu -> g_A2 bf16
// MODE 1: fc2  A=g_A2(2048x2048) B=g_W2(2048x128) -> split-K partials g_Op[z] f32
template <int MODE>
__global__ void __launch_bounds__(128) k_gemm(const float* __restrict__ bias) {
    constexpr int BM = 128, BN = 128, BK = 32;
    constexpr int Kdim = (MODE == 0) ? NGP : H1;
    constexpr int lda  = (MODE == 0) ? NGP : H1;
    constexpr int ldb  = (MODE == 0) ? H1  : H2P;
    constexpr int SPLITK = (MODE == 0) ? 1 : SPLITK2;
    constexpr int KCH  = Kdim / SPLITK;
    constexpr int NITER = KCH / BK;
    constexpr int AP = BK + 8, BP = BN + 8;

    const __nv_bfloat16* __restrict__ A = (MODE == 0) ? g_H  : g_A2;
    const __nv_bfloat16* __restrict__ B = (MODE == 0) ? g_W1 : g_W2;

    __shared__ __nv_bfloat16 As[2][BM][AP];   // 20.0 KB
    __shared__ __nv_bfloat16 Bs[2][BK][BP];   // 17.0 KB
    __shared__ float stage[4][256];           //  4.0 KB

    const int tid    = threadIdx.x;
    const int warpId = tid >> 5;
    const int lane   = tid & 31;
    const int m0 = blockIdx.x * BM;
    const int n0 = blockIdx.y * BN;
    const int kbeg = blockIdx.z * KCH;
    const int wr = warpId & 1;    // 2 row groups of 64
    const int wc = warpId >> 1;   // 2 col groups of 64

    wmma::fragment<wmma::accumulator, 16, 16, 16, float> acc[4][4];
#pragma unroll
    for (int i = 0; i < 4; i++)
#pragma unroll
        for (int j = 0; j < 4; j++) wmma::fill_fragment(acc[i][j], 0.0f);

    auto fill = [&](int st, int k0) {
#pragma unroll
        for (int q = 0; q < 4; q++) {            // A: 512 16B-chunks / 128 thr
            int c = tid + q * 128;
            int row = c >> 2, col = (c & 3) * 8;
            cp16(&As[st][row][col], A + (size_t)(m0 + row) * lda + (k0 + col));
        }
#pragma unroll
        for (int q = 0; q < 4; q++) {            // B: 512 16B-chunks / 128 thr
            int c = tid + q * 128;
            int row = c >> 4, col = (c & 15) * 8;
            cp16(&Bs[st][row][col], B + (size_t)(k0 + row) * ldb + (n0 + col));
        }
        CP_COMMIT();
    };

    fill(0, kbeg);
    if (NITER > 1) fill(1, kbeg + BK);

    for (int it = 0; it < NITER; it++) {
        int cur = it & 1;
        if (it + 1 < NITER) { CP_WAIT(1); } else { CP_WAIT(0); }
        __syncthreads();
#pragma unroll
        for (int kk = 0; kk < BK; kk += 16) {
            wmma::fragment<wmma::matrix_a, 16, 16, 16, __nv_bfloat16, wmma::row_major> af[4];
            wmma::fragment<wmma::matrix_b, 16, 16, 16, __nv_bfloat16, wmma::row_major> bf_[4];
#pragma unroll
            for (int i = 0; i < 4; i++)
                wmma::load_matrix_sync(af[i], &As[cur][wr * 64 + i * 16][kk], AP);
#pragma unroll
            for (int j = 0; j < 4; j++)
                wmma::load_matrix_sync(bf_[j], &Bs[cur][kk][wc * 64 + j * 16], BP);
#pragma unroll
            for (int i = 0; i < 4; i++)
#pragma unroll
                for (int j = 0; j < 4; j++)
                    wmma::mma_sync(acc[i][j], af[i], bf_[j], acc[i][j]);
        }
        __syncthreads();
        if (it + 2 < NITER) fill(cur, kbeg + (it + 2) * BK);
    }

    if (MODE == 1) {
        float* C = g_Op[blockIdx.z];
#pragma unroll
        for (int i = 0; i < 4; i++)
#pragma unroll
            for (int j = 0; j < 4; j++)
                wmma::store_matrix_sync(
                    C + (size_t)(m0 + wr * 64 + i * 16) * H2P + (n0 + wc * 64 + j * 16),
                    acc[i][j], H2P, wmma::mem_row_major);
    } else {
        // fused epilogue: bias + relu + bf16 -> g_A2
#pragma unroll
        for (int i = 0; i < 4; i++)
#pragma unroll
            for (int j = 0; j < 4; j++) {
                wmma::store_matrix_sync(&stage[warpId][0], acc[i][j], 16, wmma::mem_row_major);
                __syncwarp();
                int row = m0 + wr * 64 + i * 16 + (lane >> 1);
                int col = n0 + wc * 64 + j * 16 + (lane & 1) * 8;
                const float* s = &stage[warpId][(lane >> 1) * 16 + (lane & 1) * 8];
                __nv_bfloat16 v[8];
#pragma unroll
                for (int e = 0; e < 8; e++)
                    v[e] = __float2bfloat16(fmaxf(s[e] + bias[col + e], 0.f));
                *reinterpret_cast<int4*>(&g_A2[(size_t)row * H1 + col]) =
                    *reinterpret_cast<int4*>(v);
                __syncwarp();
            }
    }
}

// -------- K6: r^2 + predictor MLP, one warp per batch row --------
__global__ void __launch_bounds__(256) k_final(const float* __restrict__ others,
                                               const float* __restrict__ fc2b,
                                               const float* __restrict__ m1w,
                                               const float* __restrict__ m1b,
                                               const float* __restrict__ m2w,
                                               const float* __restrict__ m2b,
                                               float* __restrict__ out) {
    int row  = (blockIdx.x * blockDim.x + threadIdx.x) >> 5;  // 0..1023
    int lane = threadIdx.x & 31;
    float a[4], b[4];
    float sa = 0.f, sb = 0.f;
#pragma unroll
    for (int i = 0; i < 4; i++) {
        int c = lane + i * 32;
        float av = 0.f, bv = 0.f;
        if (c < H2) {
            float bias = fc2b[c];
#pragma unroll
            for (int z = 0; z < SPLITK2; z++) {
                av += g_Op[z][row * H2P + c];
                bv += g_Op[z][(BATCH + row) * H2P + c];
            }
            av += bias; bv += bias;
        }
        a[i] = av; b[i] = bv; sa += av; sb += bv;
    }
#pragma unroll
    for (int o = 16; o > 0; o >>= 1) {
        sa += __shfl_xor_sync(~0u, sa, o);
        sb += __shfl_xor_sync(~0u, sb, o);
    }
    float ma = sa * (1.f / H2), mb = sb * (1.f / H2);
    float sab = 0.f, saa = 0.f, sbb = 0.f;
#pragma unroll
    for (int i = 0; i < 4; i++) {
        int c = lane + i * 32;
        if (c < H2) {
            float da = a[i] - ma, db = b[i] - mb;
            sab += da * db; saa += da * da; sbb += db * db;
        }
    }
#pragma unroll
    for (int o = 16; o > 0; o >>= 1) {
        sab += __shfl_xor_sync(~0u, sab, o);
        saa += __shfl_xor_sync(~0u, saa, o);
        sbb += __shfl_xor_sync(~0u, sbb, o);
    }
    if (lane == 0) {
        float corr = sab / (sqrtf(saa) * sqrtf(sbb));
        float z[5];
        z[0] = corr * corr;
#pragma unroll
        for (int i = 0; i < 4; i++) z[i + 1] = others[row * 4 + i];
        float h[4];
#pragma unroll
        for (int j = 0; j < 4; j++) {
            float s = m1b[j];
#pragma unroll
            for (int i = 0; i < 5; i++) s += z[i] * m1w[i * 4 + j];
            h[j] = fmaxf(s, 0.f);
        }
#pragma unroll
        for (int k = 0; k < 2; k++) {
            float s = m2b[k];
#pragma unroll
            for (int j = 0; j < 4; j++) s += h[j] * m2w[j * 2 + k];
            out[row * 2 + k] = s;
        }
    }
}

extern "C" void kernel_launch(void* const* d_in, const int* in_sizes, int n_in,
                              void* d_out, int out_size) {
    const float* in1    = (const float*)d_in[0];
    const float* in2    = (const float*)d_in[1];
    const int*   edges  = (const int*)d_in[2];
    const float* others = (const float*)d_in[3];
    const float* gw     = (const float*)d_in[4];
    const float* gb     = (const float*)d_in[5];
    const float* w1     = (const float*)d_in[6];
    const float* b1     = (const float*)d_in[7];
    const float* w2     = (const float*)d_in[8];
    const float* b2     = (const float*)d_in[9];
    const float* m1w    = (const float*)d_in[10];
    const float* m1b    = (const float*)d_in[11];
    const float* m2w    = (const float*)d_in[12];
    const float* m2b    = (const float*)d_in[13];
    float* out = (float*)d_out;

    k_pack <<<NNODE / 2 / 256, 256>>>(in1, in2);             // 1956 blocks
    k_prep <<<(NG * H1 + H1 * H2 + 255) / 256, 256>>>(w1, w2);
    k_edges<<<NEDGE / 8 / 256, 256>>>(edges);                // 10000 blocks
    k_h    <<<NNODE / 2 / 256, 256>>>(gw, gb);
    k_gemm<0><<<dim3(16, 16, 1), 128>>>(b1);                 // fc1 + fused bias/relu
    k_gemm<1><<<dim3(16, 1, SPLITK2), 128>>>(nullptr);       // fc2 split-K partials
    k_final<<<128, 256>>>(others, b2, m1w, m1b, m2w, m2b, out);
}